// round 4
// baseline (speedup 1.0000x reference)
#include <cuda_runtime.h>

#define N_NODES 100000
#define N_EDGES 3200000
#define F_IN    256
#define F_HID   64
#define F_OUT   40

// ---------------- scratch (device globals: alloc-free) ----------------
__device__ int    g_deg [N_NODES];
__device__ float  g_dinv[N_NODES];
__device__ int    g_src [N_EDGES];
__device__ int    g_dst [N_EDGES];
__device__ float  g_norm[N_EDGES];
__device__ float4 g_h   [N_NODES * 16];  // h1: [N,64] as float4
__device__ float4 g_agg1[N_NODES * 16];  // aggregated layer-1
__device__ float4 g_h2  [N_NODES * 10];  // h2: [N,40] as float4

// PTX ISA 8.1+ vector reduction (sm_90+): no return value, 1 LSU op per 16B.
__device__ __forceinline__ void red_add_f4(float4* addr, float a, float b, float c, float d) {
    asm volatile("red.global.add.v4.f32 [%0], {%1,%2,%3,%4};"
                 :: "l"(addr), "f"(a), "f"(b), "f"(c), "f"(d) : "memory");
}

// ---------------- degree / norm prep ----------------
__global__ void k_init_deg() {
    int n = blockIdx.x * blockDim.x + threadIdx.x;
    if (n < N_NODES) g_deg[n] = 1;  // self-loop
}

// edge_index is int32: JAX demotes jnp.int64 to int32 when x64 is disabled (default).
__global__ void k_count_deg(const int* __restrict__ ei) {
    int e = blockIdx.x * blockDim.x + threadIdx.x;
    if (e < N_EDGES) {
        int d = __ldg(&ei[N_EDGES + e]);
        atomicAdd(&g_deg[d], 1);
    }
}

__global__ void k_dinv() {
    int n = blockIdx.x * blockDim.x + threadIdx.x;
    if (n < N_NODES) g_dinv[n] = rsqrtf((float)g_deg[n]);
}

__global__ void k_prep_edges(const int* __restrict__ ei) {
    int e = blockIdx.x * blockDim.x + threadIdx.x;
    if (e < N_EDGES) {
        int s = __ldg(&ei[e]);
        int d = __ldg(&ei[N_EDGES + e]);
        g_src[e]  = s;
        g_dst[e]  = d;
        g_norm[e] = g_dinv[s] * g_dinv[d];
    }
}

// ---------------- GEMM1: h = x @ W1   [N,256]x[256,64] ----------------
__global__ __launch_bounds__(256) void k_gemm1(const float* __restrict__ x,
                                               const float* __restrict__ W1) {
    __shared__ float w[128 * 64];
    int node = blockIdx.x * 256 + threadIdx.x;
    float acc[64];
#pragma unroll
    for (int j = 0; j < 64; j++) acc[j] = 0.f;

#pragma unroll 1
    for (int kb = 0; kb < 2; kb++) {
        // stage W1[kb*128 .. +128][0..64) into smem (coalesced float4)
        const float4* wsrc = (const float4*)(W1 + kb * 128 * 64);
        float4* wdst = (float4*)w;
#pragma unroll
        for (int i = 0; i < 8; i++)
            wdst[threadIdx.x + i * 256] = wsrc[threadIdx.x + i * 256];
        __syncthreads();

        if (node < N_NODES) {
            const float4* xr = (const float4*)(x + (size_t)node * F_IN + kb * 128);
#pragma unroll 4
            for (int k4 = 0; k4 < 32; k4++) {
                float4 xv = xr[k4];
#pragma unroll
                for (int kk = 0; kk < 4; kk++) {
                    float xk = (kk == 0) ? xv.x : (kk == 1) ? xv.y : (kk == 2) ? xv.z : xv.w;
                    const float4* wr = (const float4*)(w + (k4 * 4 + kk) * 64);
#pragma unroll
                    for (int j = 0; j < 16; j++) {
                        float4 wv = wr[j];
                        acc[4 * j + 0] += xk * wv.x;
                        acc[4 * j + 1] += xk * wv.y;
                        acc[4 * j + 2] += xk * wv.z;
                        acc[4 * j + 3] += xk * wv.w;
                    }
                }
            }
        }
        __syncthreads();
    }

    if (node < N_NODES) {
        float4* out = &g_h[node * 16];
#pragma unroll
        for (int j = 0; j < 16; j++)
            out[j] = make_float4(acc[4 * j], acc[4 * j + 1], acc[4 * j + 2], acc[4 * j + 3]);
    }
}

// ---------------- layer-1 aggregation ----------------
// init with self-loop contribution: agg1[n] = dinv[n]^2 * h[n]
__global__ void k_init_agg1() {
    int i = blockIdx.x * blockDim.x + threadIdx.x;
    if (i < N_NODES * 16) {
        int n = i >> 4;
        float s = g_dinv[n];
        s = s * s;
        float4 v = g_h[i];
        g_agg1[i] = make_float4(s * v.x, s * v.y, s * v.z, s * v.w);
    }
}

// thread = (edge, 16B-chunk); 16 chunks of 4 floats cover 64 features
__global__ void k_scatter1() {
    unsigned gid = blockIdx.x * blockDim.x + threadIdx.x;
    // gid < E*16 exactly (grid sized to match)
    int e = gid >> 4;
    int c = gid & 15;
    int s = g_src[e];
    int d = g_dst[e];
    float nm = g_norm[e];
    float4 v = g_h[s * 16 + c];
    red_add_f4(&g_agg1[d * 16 + c], nm * v.x, nm * v.y, nm * v.z, nm * v.w);
}

// ---------------- GEMM2: h2 = relu(agg1 + b1) @ W2   [N,64]x[64,40] ----------------
__global__ __launch_bounds__(256) void k_gemm2(const float* __restrict__ W2,
                                               const float* __restrict__ b1) {
    __shared__ float w[64 * 40];
    __shared__ float bs[64];
    int node = blockIdx.x * 256 + threadIdx.x;

    // stage W2 + b1
    const float4* wsrc = (const float4*)W2;
    float4* wdst = (float4*)w;
    for (int i = threadIdx.x; i < 64 * 10; i += 256) wdst[i] = wsrc[i];
    if (threadIdx.x < 64) bs[threadIdx.x] = b1[threadIdx.x];
    __syncthreads();

    if (node >= N_NODES) return;

    float acc[40];
#pragma unroll
    for (int j = 0; j < 40; j++) acc[j] = 0.f;

    const float4* ar = &g_agg1[node * 16];
#pragma unroll 4
    for (int k4 = 0; k4 < 16; k4++) {
        float4 a = ar[k4];
#pragma unroll
        for (int kk = 0; kk < 4; kk++) {
            int k = k4 * 4 + kk;
            float av = (kk == 0) ? a.x : (kk == 1) ? a.y : (kk == 2) ? a.z : a.w;
            float v = fmaxf(av + bs[k], 0.f);
            const float4* wr = (const float4*)(w + k * 40);
#pragma unroll
            for (int j = 0; j < 10; j++) {
                float4 wv = wr[j];
                acc[4 * j + 0] += v * wv.x;
                acc[4 * j + 1] += v * wv.y;
                acc[4 * j + 2] += v * wv.z;
                acc[4 * j + 3] += v * wv.w;
            }
        }
    }

    float4* out = &g_h2[node * 10];
#pragma unroll
    for (int j = 0; j < 10; j++)
        out[j] = make_float4(acc[4 * j], acc[4 * j + 1], acc[4 * j + 2], acc[4 * j + 3]);
}

// ---------------- layer-2 aggregation (into d_out) ----------------
__global__ void k_init_agg2(float4* __restrict__ out) {
    int i = blockIdx.x * blockDim.x + threadIdx.x;
    if (i < N_NODES * 10) {
        int n = (unsigned)i / 10u;
        float s = g_dinv[n];
        s = s * s;
        float4 v = g_h2[i];
        out[i] = make_float4(s * v.x, s * v.y, s * v.z, s * v.w);
    }
}

__global__ void k_scatter2(float4* __restrict__ out) {
    unsigned gid = blockIdx.x * blockDim.x + threadIdx.x;
    if (gid >= (unsigned)N_EDGES * 10u) return;
    unsigned e = gid / 10u;
    unsigned c = gid - e * 10u;
    int s = g_src[e];
    int d = g_dst[e];
    float nm = g_norm[e];
    float4 v = g_h2[s * 10 + c];
    red_add_f4(&out[d * 10 + c], nm * v.x, nm * v.y, nm * v.z, nm * v.w);
}

// ---------------- log-softmax (+b2), in-place on d_out; warp per node ----------------
__global__ __launch_bounds__(128) void k_logsoftmax(float* __restrict__ out,
                                                    const float* __restrict__ b2) {
    int warp = (blockIdx.x * 128 + threadIdx.x) >> 5;
    int lane = threadIdx.x & 31;
    if (warp >= N_NODES) return;
    float* row = out + (size_t)warp * F_OUT;

    float v0 = row[lane] + __ldg(&b2[lane]);                 // lanes 0..31 all valid (<40)
    float v1 = (lane < 8) ? (row[32 + lane] + __ldg(&b2[32 + lane])) : -3.4e38f;

    float m = fmaxf(v0, v1);
#pragma unroll
    for (int o = 16; o > 0; o >>= 1)
        m = fmaxf(m, __shfl_xor_sync(0xFFFFFFFFu, m, o));

    float s = expf(v0 - m) + ((lane < 8) ? expf(v1 - m) : 0.f);
#pragma unroll
    for (int o = 16; o > 0; o >>= 1)
        s += __shfl_xor_sync(0xFFFFFFFFu, s, o);

    float ls = logf(s);
    row[lane] = v0 - m - ls;
    if (lane < 8) row[32 + lane] = v1 - m - ls;
}

// ---------------- launch ----------------
extern "C" void kernel_launch(void* const* d_in, const int* in_sizes, int n_in,
                              void* d_out, int out_size) {
    const float* x  = (const float*)d_in[0];
    const int*   ei = (const int*)d_in[1];   // int32: JAX default (x64 disabled)
    const float* W1 = (const float*)d_in[2];
    const float* b1 = (const float*)d_in[3];
    const float* W2 = (const float*)d_in[4];
    const float* b2 = (const float*)d_in[5];
    float*       out = (float*)d_out;

    const int TB = 256;
    k_init_deg  <<<(N_NODES + TB - 1) / TB, TB>>>();
    k_count_deg <<<(N_EDGES + TB - 1) / TB, TB>>>(ei);
    k_dinv      <<<(N_NODES + TB - 1) / TB, TB>>>();
    k_prep_edges<<<(N_EDGES + TB - 1) / TB, TB>>>(ei);

    k_gemm1     <<<(N_NODES + 255) / 256, 256>>>(x, W1);
    k_init_agg1 <<<(N_NODES * 16 + TB - 1) / TB, TB>>>();
    k_scatter1  <<<(N_EDGES * 16) / TB, TB>>>();            // E*16 divisible by 256

    k_gemm2     <<<(N_NODES + 255) / 256, 256>>>(W2, b1);
    k_init_agg2 <<<(N_NODES * 10 + TB - 1) / TB, TB>>>((float4*)out);
    k_scatter2  <<<((unsigned)N_EDGES * 10u + TB - 1) / TB, TB>>>((float4*)out);

    k_logsoftmax<<<(N_NODES + 3) / 4, 128>>>(out, b2);
}

// round 5
// speedup vs baseline: 1.3493x; 1.3493x over previous
#include <cuda_runtime.h>

#define N_NODES 100000
#define N_EDGES 3200000
#define F_IN    256
#define F_HID   64
#define F_OUT   40
#define SCAN_B  512
#define N_SCANB ((N_NODES + SCAN_B - 1) / SCAN_B)   // 196

// ---------------- scratch (device globals: alloc-free) ----------------
__device__ int   g_dege  [N_NODES];      // degree WITHOUT self-loop
__device__ float g_dinv  [N_NODES];
__device__ int   g_rowptr[N_NODES];      // exclusive prefix of g_dege
__device__ int   g_cursor[N_NODES];      // fill cursor for counting sort
__device__ int   g_bsum  [256];          // block partials for scan
__device__ int2  g_edges [N_EDGES];      // dst-sorted: {src, norm as bits}
__device__ float g_h   [N_NODES * 64];   // h1 = x@W1
__device__ float g_agg1[N_NODES * 64];   // normalized aggregation of h1
__device__ float g_h2  [N_NODES * 40];   // relu(agg1+b1)@W2

// ---------------- degree / norm prep ----------------
__global__ void k_init_deg() {
    int n = blockIdx.x * blockDim.x + threadIdx.x;
    if (n < N_NODES) g_dege[n] = 0;
}

__global__ void k_count_deg(const int* __restrict__ ei) {
    int e = blockIdx.x * blockDim.x + threadIdx.x;
    if (e < N_EDGES) atomicAdd(&g_dege[__ldg(&ei[N_EDGES + e])], 1);
}

__global__ void k_dinv() {
    int n = blockIdx.x * blockDim.x + threadIdx.x;
    if (n < N_NODES) g_dinv[n] = rsqrtf((float)(g_dege[n] + 1));  // +1 self-loop
}

// ---------------- 3-step exclusive scan of g_dege -> g_rowptr ----------------
__global__ __launch_bounds__(SCAN_B) void k_scan1() {
    __shared__ int sm[SCAN_B];
    int t = threadIdx.x;
    int i = blockIdx.x * SCAN_B + t;
    int v = (i < N_NODES) ? g_dege[i] : 0;
    sm[t] = v;
    __syncthreads();
    for (int o = 1; o < SCAN_B; o <<= 1) {
        int x = (t >= o) ? sm[t - o] : 0;
        __syncthreads();
        sm[t] += x;
        __syncthreads();
    }
    if (i < N_NODES) g_rowptr[i] = sm[t] - v;        // exclusive
    if (t == SCAN_B - 1) g_bsum[blockIdx.x] = sm[t]; // block total
}

__global__ __launch_bounds__(256) void k_scan2() {   // single block
    __shared__ int sm[256];
    int t = threadIdx.x;
    int v = (t < N_SCANB) ? g_bsum[t] : 0;
    sm[t] = v;
    __syncthreads();
    for (int o = 1; o < 256; o <<= 1) {
        int x = (t >= o) ? sm[t - o] : 0;
        __syncthreads();
        sm[t] += x;
        __syncthreads();
    }
    g_bsum[t] = sm[t] - v;                           // exclusive block offsets
}

__global__ void k_scan3() {
    int i = blockIdx.x * blockDim.x + threadIdx.x;
    if (i < N_NODES) {
        int r = g_rowptr[i] + g_bsum[i / SCAN_B];
        g_rowptr[i] = r;
        g_cursor[i] = r;
    }
}

// ---------------- counting sort: edges bucketed by dst ----------------
__global__ void k_sort(const int* __restrict__ ei) {
    int e = blockIdx.x * blockDim.x + threadIdx.x;
    if (e < N_EDGES) {
        int s = __ldg(&ei[e]);
        int d = __ldg(&ei[N_EDGES + e]);
        float nm = g_dinv[s] * g_dinv[d];
        int pos = atomicAdd(&g_cursor[d], 1);
        g_edges[pos] = make_int2(s, __float_as_int(nm));
    }
}

// ---------------- GEMM1: h = x @ W1   [N,256]x[256,64] ----------------
__global__ __launch_bounds__(256) void k_gemm1(const float* __restrict__ x,
                                               const float* __restrict__ W1) {
    __shared__ float w[128 * 64];
    int node = blockIdx.x * 256 + threadIdx.x;
    float acc[64];
#pragma unroll
    for (int j = 0; j < 64; j++) acc[j] = 0.f;

#pragma unroll 1
    for (int kb = 0; kb < 2; kb++) {
        const float4* wsrc = (const float4*)(W1 + kb * 128 * 64);
        float4* wdst = (float4*)w;
#pragma unroll
        for (int i = 0; i < 8; i++)
            wdst[threadIdx.x + i * 256] = wsrc[threadIdx.x + i * 256];
        __syncthreads();

        if (node < N_NODES) {
            const float4* xr = (const float4*)(x + (size_t)node * F_IN + kb * 128);
#pragma unroll 4
            for (int k4 = 0; k4 < 32; k4++) {
                float4 xv = xr[k4];
#pragma unroll
                for (int kk = 0; kk < 4; kk++) {
                    float xk = (kk == 0) ? xv.x : (kk == 1) ? xv.y : (kk == 2) ? xv.z : xv.w;
                    const float4* wr = (const float4*)(w + (k4 * 4 + kk) * 64);
#pragma unroll
                    for (int j = 0; j < 16; j++) {
                        float4 wv = wr[j];
                        acc[4 * j + 0] += xk * wv.x;
                        acc[4 * j + 1] += xk * wv.y;
                        acc[4 * j + 2] += xk * wv.z;
                        acc[4 * j + 3] += xk * wv.w;
                    }
                }
            }
        }
        __syncthreads();
    }

    if (node < N_NODES) {
        float4* out = (float4*)&g_h[node * 64];
#pragma unroll
        for (int j = 0; j < 16; j++)
            out[j] = make_float4(acc[4 * j], acc[4 * j + 1], acc[4 * j + 2], acc[4 * j + 3]);
    }
}

// ---------------- layer-1 aggregation: warp per node, CSR gather ----------------
__global__ __launch_bounds__(256) void k_agg1() {
    int node = (blockIdx.x * 256 + threadIdx.x) >> 5;
    int lane = threadIdx.x & 31;
    if (node >= N_NODES) return;

    float dv = g_dinv[node];
    float s2 = dv * dv;
    float a0 = s2 * g_h[node * 64 + lane];
    float a1 = s2 * g_h[node * 64 + 32 + lane];

    int start = g_rowptr[node];
    int cnt   = g_dege[node];
    for (int base = 0; base < cnt; base += 32) {
        int idx = base + lane;
        int2 rec = (idx < cnt) ? g_edges[start + idx] : make_int2(0, 0);
        int m = min(32, cnt - base);
        for (int j = 0; j < m; j++) {
            int   src = __shfl_sync(0xFFFFFFFFu, rec.x, j);
            float nm  = __int_as_float(__shfl_sync(0xFFFFFFFFu, rec.y, j));
            a0 += nm * g_h[src * 64 + lane];
            a1 += nm * g_h[src * 64 + 32 + lane];
        }
    }
    g_agg1[node * 64 + lane]      = a0;
    g_agg1[node * 64 + 32 + lane] = a1;
}

// ---------------- GEMM2: h2 = relu(agg1 + b1) @ W2   [N,64]x[64,40] ----------------
__global__ __launch_bounds__(256) void k_gemm2(const float* __restrict__ W2,
                                               const float* __restrict__ b1) {
    __shared__ float w[64 * 40];
    __shared__ float bs[64];
    int node = blockIdx.x * 256 + threadIdx.x;

    const float4* wsrc = (const float4*)W2;
    float4* wdst = (float4*)w;
    for (int i = threadIdx.x; i < 64 * 10; i += 256) wdst[i] = wsrc[i];
    if (threadIdx.x < 64) bs[threadIdx.x] = b1[threadIdx.x];
    __syncthreads();

    if (node >= N_NODES) return;

    float acc[40];
#pragma unroll
    for (int j = 0; j < 40; j++) acc[j] = 0.f;

    const float4* ar = (const float4*)&g_agg1[node * 64];
#pragma unroll 4
    for (int k4 = 0; k4 < 16; k4++) {
        float4 a = ar[k4];
#pragma unroll
        for (int kk = 0; kk < 4; kk++) {
            int k = k4 * 4 + kk;
            float av = (kk == 0) ? a.x : (kk == 1) ? a.y : (kk == 2) ? a.z : a.w;
            float v = fmaxf(av + bs[k], 0.f);
            const float4* wr = (const float4*)(w + k * 40);
#pragma unroll
            for (int j = 0; j < 10; j++) {
                float4 wv = wr[j];
                acc[4 * j + 0] += v * wv.x;
                acc[4 * j + 1] += v * wv.y;
                acc[4 * j + 2] += v * wv.z;
                acc[4 * j + 3] += v * wv.w;
            }
        }
    }

    float4* out = (float4*)&g_h2[node * 40];
#pragma unroll
    for (int j = 0; j < 10; j++)
        out[j] = make_float4(acc[4 * j], acc[4 * j + 1], acc[4 * j + 2], acc[4 * j + 3]);
}

// ------- layer-2 aggregation + b2 + log-softmax fused: warp per node -------
__global__ __launch_bounds__(256) void k_agg2(float* __restrict__ out,
                                              const float* __restrict__ b2) {
    int node = (blockIdx.x * 256 + threadIdx.x) >> 5;
    int lane = threadIdx.x & 31;
    if (node >= N_NODES) return;

    float dv = g_dinv[node];
    float s2 = dv * dv;
    float a0 = s2 * g_h2[node * 40 + lane];
    float a1 = (lane < 8) ? s2 * g_h2[node * 40 + 32 + lane] : 0.f;

    int start = g_rowptr[node];
    int cnt   = g_dege[node];
    for (int base = 0; base < cnt; base += 32) {
        int idx = base + lane;
        int2 rec = (idx < cnt) ? g_edges[start + idx] : make_int2(0, 0);
        int m = min(32, cnt - base);
        for (int j = 0; j < m; j++) {
            int   src = __shfl_sync(0xFFFFFFFFu, rec.x, j);
            float nm  = __int_as_float(__shfl_sync(0xFFFFFFFFu, rec.y, j));
            a0 += nm * g_h2[src * 40 + lane];
            if (lane < 8) a1 += nm * g_h2[src * 40 + 32 + lane];
        }
    }

    float v0 = a0 + __ldg(&b2[lane]);
    float v1 = (lane < 8) ? a1 + __ldg(&b2[32 + lane]) : -3.4e38f;

    float mx = fmaxf(v0, v1);
#pragma unroll
    for (int o = 16; o > 0; o >>= 1)
        mx = fmaxf(mx, __shfl_xor_sync(0xFFFFFFFFu, mx, o));

    float s = expf(v0 - mx) + ((lane < 8) ? expf(v1 - mx) : 0.f);
#pragma unroll
    for (int o = 16; o > 0; o >>= 1)
        s += __shfl_xor_sync(0xFFFFFFFFu, s, o);

    float ls = logf(s);
    out[node * 40 + lane] = v0 - mx - ls;
    if (lane < 8) out[node * 40 + 32 + lane] = v1 - mx - ls;
}

// ---------------- launch ----------------
extern "C" void kernel_launch(void* const* d_in, const int* in_sizes, int n_in,
                              void* d_out, int out_size) {
    const float* x  = (const float*)d_in[0];
    const int*   ei = (const int*)d_in[1];   // int32 (JAX x64 disabled)
    const float* W1 = (const float*)d_in[2];
    const float* b1 = (const float*)d_in[3];
    const float* W2 = (const float*)d_in[4];
    const float* b2 = (const float*)d_in[5];
    float*       out = (float*)d_out;

    const int TB = 256;
    k_init_deg <<<(N_NODES + TB - 1) / TB, TB>>>();
    k_count_deg<<<(N_EDGES + TB - 1) / TB, TB>>>(ei);
    k_dinv     <<<(N_NODES + TB - 1) / TB, TB>>>();
    k_scan1    <<<N_SCANB, SCAN_B>>>();
    k_scan2    <<<1, 256>>>();
    k_scan3    <<<(N_NODES + TB - 1) / TB, TB>>>();
    k_sort     <<<(N_EDGES + TB - 1) / TB, TB>>>(ei);

    k_gemm1    <<<(N_NODES + 255) / 256, 256>>>(x, W1);
    k_agg1     <<<(N_NODES * 32 + TB - 1) / TB, TB>>>();   // warp per node
    k_gemm2    <<<(N_NODES + 255) / 256, 256>>>(W2, b1);
    k_agg2     <<<(N_NODES * 32 + TB - 1) / TB, TB>>>(out, b2);
}